// round 6
// baseline (speedup 1.0000x reference)
#include <cuda_runtime.h>
#include <cuda_bf16.h>
#include <math.h>

#define BATCH 32
#define HW    512
#define NPIX  (HW*HW)            // 262144
#define WPR   16                 // 32-bit words per row
#define G4PB  (NPIX/4)           // 65536 float4 groups per batch
#define NTHR  254

#define ROWS  16                 // rows per strip
#define NSTR  (HW/ROWS)          // 32 strips
#define HALO  (ROWS+4)           // 20
#define NLW   (HALO*WPR)         // 320 halo words
#define SW    (ROWS*WPR)         // 256 strip words (== blockDim)
#define CAP   (SW*8)             // 2048 staged entries max

// ---------------- device scratch (overwrite-style; counters self-reset via wrap) ----------------
__device__ unsigned g_histp[BATCH][NSTR][256];   // otsu-hist partials
__device__ unsigned g_ccnt [BATCH][NSTR][256];   // class-bin count partials
__device__ float    g_cp   [BATCH][NSTR][256];   // class-bin sum(p)
__device__ float    g_cp2  [BATCH][NSTR][256];   // class-bin sum(p^2)
__device__ unsigned g_cntp [BATCH][NSTR];        // mask-count partials
__device__ float    g_lossper[BATCH];
__device__ int      g_validb[BATCH];
__device__ unsigned g_done1[BATCH];              // wraps 0..NSTR-1
__device__ unsigned g_done2;                     // wraps 0..BATCH-1

// ======== single fused kernel ========
__global__ __launch_bounds__(256) void fusedKernel(const float* __restrict__ labels,
                                                   const float* __restrict__ images,
                                                   const float* __restrict__ preds,
                                                   float* __restrict__ out) {
    const int b = blockIdx.y, strip = blockIdx.x;
    const int row0 = strip * ROWS;
    const int tid = threadIdx.x, lane = tid & 31, warp = tid >> 5;

    __shared__ unsigned lw[NLW];
    __shared__ unsigned hwv[NLW];
    __shared__ unsigned stage[CAP];
    __shared__ unsigned sh_hist[256];
    __shared__ unsigned cls_cnt[256];
    __shared__ float    cls_p[256];
    __shared__ float    cls_p2[256];
    __shared__ unsigned s_n;
    __shared__ unsigned wcnt[8];
    __shared__ unsigned s_rank, s_rank2;
    __shared__ int      s_k1, s_k2;
    __shared__ float    s_total;

    sh_hist[tid] = 0u; cls_cnt[tid] = 0u; cls_p[tid] = 0.0f; cls_p2[tid] = 0.0f;
    if (tid == 0) s_n = 0u;
    for (int w = tid; w < NLW; w += 256) lw[w] = 0u;
    __syncthreads();

    // ---- phase A: pack label bits from float4 stream ----
    const float4* lab4 = (const float4*)labels + (size_t)b * G4PB;
    for (int q = tid; q < HALO * 128; q += 256) {
        int r = q >> 7, c4 = q & 127;
        int grow = row0 - 2 + r;
        if (grow >= 0 && grow < HW) {
            float4 v = __ldg(lab4 + grow * 128 + c4);
            unsigned nib = (unsigned)(v.x > 0.0f) | ((unsigned)(v.y > 0.0f) << 1)
                         | ((unsigned)(v.z > 0.0f) << 2) | ((unsigned)(v.w > 0.0f) << 3);
            if (nib) atomicOr(&lw[r * WPR + (c4 >> 3)], nib << ((c4 & 7) * 4));
        }
    }
    __syncthreads();

    // ---- phase B: horizontal dilation radius 2 ----
    for (int w = tid; w < NLW; w += 256) {
        int wc = w & 15;
        unsigned C = lw[w];
        unsigned L = wc ? lw[w - 1] : 0u;
        unsigned R = (wc < 15) ? lw[w + 1] : 0u;
        hwv[w] = C | (C << 1) | (C << 2) | (C >> 1) | (C >> 2)
               | (L >> 31) | (L >> 30) | (R << 31) | (R << 30);
    }
    __syncthreads();

    // ---- phase C: vertical OR + count + warp-aggregated staging (1 word/thread) ----
    {
        int w = tid;
        int r = w >> 4, wc = w & 15;
        unsigned m = hwv[w] | hwv[w + 16] | hwv[w + 32] | hwv[w + 48] | hwv[w + 64];
        unsigned cnt = __popc(m);

        unsigned nz = 0;
        #pragma unroll
        for (int k = 0; k < 8; k++) if ((m >> (k * 4)) & 0xFu) nz |= 1u << k;
        unsigned ne = __popc(nz);

        unsigned off = ne;
        #pragma unroll
        for (int o = 1; o < 32; o <<= 1) {
            unsigned v = __shfl_up_sync(0xffffffffu, off, o);
            if (lane >= o) off += v;
        }
        unsigned tot = __shfl_sync(0xffffffffu, off, 31);
        unsigned exc = off - ne;
        unsigned base = 0;
        if (lane == 31) base = atomicAdd(&s_n, tot);
        base = __shfl_sync(0xffffffffu, base, 31);

        unsigned gw8 = ((row0 + r) * WPR + wc) * 8;
        unsigned pos = base + exc;
        #pragma unroll
        for (int k = 0; k < 8; k++) if (nz & (1u << k)) {
            unsigned nib = (m >> (k * 4)) & 0xFu;
            stage[pos++] = (nib << 16) | (gw8 + k);
        }

        #pragma unroll
        for (int o = 16; o; o >>= 1) cnt += __shfl_down_sync(0xffffffffu, cnt, o);
        if (lane == 0) wcnt[warp] = cnt;
    }
    __syncthreads();

    // ---- phase D: gather img+pred at active groups, build all 4 histograms ----
    const unsigned n = s_n;
    const float4* img4 = (const float4*)images + (size_t)b * G4PB;
    const float4* prd4 = (const float4*)preds  + (size_t)b * G4PB;
    const float SCALEF = 256.0f / 255.0f;
    for (unsigned i = tid; i < n; i += 256) {
        unsigned e = stage[i];
        unsigned g = e & 0xFFFFu, nib = e >> 16;
        float4 iv = __ldg(img4 + g);
        float4 pv = __ldg(prd4 + g);
        float is[4] = {iv.x, iv.y, iv.z, iv.w};
        float ps[4] = {pv.x, pv.y, pv.z, pv.w};
        #pragma unroll
        for (int k = 0; k < 4; k++) if (nib & (1u << k)) {
            float v255 = is[k] * 255.0f;
            int idx = (int)floorf(v255 * SCALEF);          // otsu bin (== reference)
            idx = idx < 0 ? 0 : (idx > 255 ? 255 : idx);
            atomicAdd(&sh_hist[idx], 1u);
            int j = (int)floorf(v255);                     // class bin: floor(im*255)
            j = j < 0 ? 0 : (j > 255 ? 255 : j);
            float p = ps[k];
            atomicAdd(&cls_cnt[j], 1u);
            atomicAdd(&cls_p[j], p);
            atomicAdd(&cls_p2[j], p * p);
        }
    }
    __syncthreads();

    // ---- write per-strip partials ----
    g_histp[b][strip][tid] = sh_hist[tid];
    g_ccnt [b][strip][tid] = cls_cnt[tid];
    g_cp   [b][strip][tid] = cls_p[tid];
    g_cp2  [b][strip][tid] = cls_p2[tid];
    if (tid == 0) {
        unsigned t = 0;
        #pragma unroll
        for (int i = 0; i < 8; i++) t += wcnt[i];
        g_cntp[b][strip] = t;
    }

    // ---- election 1: last strip-block of this batch ----
    __threadfence();
    __syncthreads();
    if (tid == 0) s_rank = atomicInc(&g_done1[b], NSTR - 1);
    __syncthreads();
    if (s_rank != NSTR - 1) return;
    __threadfence();

    // ---- Otsu for batch b (alias arrays onto stage/sh_hist/cls_cnt) ----
    {
        float* h     = (float*)stage;
        float* a     = (float*)stage + 256;
        float* cmv   = (float*)stage + 512;
        float* term2 = (float*)stage + 768;
        unsigned char* w2pos = (unsigned char*)((float*)stage + 1024);
        float* sbest = (float*)sh_hist;
        int*   sidx  = (int*)cls_cnt;

        unsigned hc = 0;
        #pragma unroll
        for (int s = 0; s < NSTR; s++) hc += __ldcg(&g_histp[b][s][tid]);
        if (tid == 0) {
            unsigned t = 0;
            #pragma unroll
            for (int s = 0; s < NSTR; s++) t += __ldcg(&g_cntp[b][s]);
            s_total = (float)t;
        }
        __syncthreads();
        h[tid] = (float)hc / s_total;
        __syncthreads();

        if (tid == 0) {                          // sequential cumsum == jnp order
            float c = 0.0f, c2 = 0.0f;
            for (int i = 0; i < 256; i++) {
                c  += h[i];              a[i]   = c;
                c2 += h[i] * (float)i;   cmv[i] = c2;
            }
        }
        __syncthreads();

        const float tm = cmv[255];
        const float s = 1e-8f;
        if (tid < NTHR) {
            float cb = a[tid], w2 = 1.0f - cb;
            float mean2 = (tm - cmv[tid]) / (w2 + s);
            float d2 = mean2 - tm;
            term2[tid] = w2 * (d2 * d2);
            w2pos[tid] = w2 > 0.0f;
        }
        __syncthreads();

        float best = -1.0f;
        int bflat = 0x7fffffff;
        if (tid < NTHR) {
            const int i = tid;
            float w0 = a[i], m0 = cmv[i];
            float mean0 = m0 / (w0 + s);
            float d0 = mean0 - tm;
            float term0 = w0 * (d0 * d0);
            bool p0 = w0 > 0.0f;
            for (int j = 0; j < NTHR; j++) {
                float w1 = a[j] - w0;
                float mean1 = (cmv[j] - m0) / (w1 + s);
                float d1 = mean1 - tm;
                float bv = term0 + w1 * (d1 * d1) + term2[j];
                bv = (p0 && w1 > 0.0f && w2pos[j]) ? bv : 0.0f;
                if (bv > best) { best = bv; bflat = i * NTHR + j; }
            }
        }
        sbest[tid] = best; sidx[tid] = bflat;
        __syncthreads();
        for (int st = 128; st; st >>= 1) {       // min-flat tie-break == jnp.argmax
            if (tid < st) {
                if (sbest[tid + st] > sbest[tid] ||
                    (sbest[tid + st] == sbest[tid] && sidx[tid + st] < sidx[tid])) {
                    sbest[tid] = sbest[tid + st];
                    sidx[tid]  = sidx[tid + st];
                }
            }
            __syncthreads();
        }
        if (tid == 0) {
            int am = sidx[0];
            s_k1 = am / NTHR + 1;                // im >= t1  <=>  j >= k1
            s_k2 = am % NTHR + 1;
        }
        __syncthreads();
    }

    // ---- closed-form loss for batch b from class-bin partials ----
    {
        float c = 0.0f, p = 0.0f, q = 0.0f;
        #pragma unroll
        for (int s = 0; s < NSTR; s++) {
            c += (float)__ldcg(&g_ccnt[b][s][tid]);
            p += __ldcg(&g_cp[b][s][tid]);
            q += __ldcg(&g_cp2[b][s][tid]);
        }
        float term = q;
        if (tid >= s_k2)      term += c - 2.0f * p;          // (1-p)^2 = 1-2p+p^2
        else if (tid >= s_k1) term += 0.25f * c - p;         // (0.5-p)^2
        float* red = (float*)lw;
        red[tid] = term;
        __syncthreads();
        for (int st = 128; st; st >>= 1) {
            if (tid < st) red[tid] += red[tid + st];
            __syncthreads();
        }
        if (tid == 0) {
            float sm = s_total + 1e-8f;
            bool valid = sm > 1e-8f;
            g_lossper[b] = valid ? (red[0] / sm) : 0.0f;
            g_validb[b] = valid ? 1 : 0;
        }
    }

    // ---- election 2: last finished batch writes the scalar ----
    __threadfence();
    __syncthreads();
    if (tid == 0) s_rank2 = atomicInc(&g_done2, BATCH - 1);
    __syncthreads();
    if (s_rank2 != BATCH - 1) return;
    __threadfence();

    if (tid < 32) {
        float lp = __ldcg(&g_lossper[tid]);
        int   c  = __ldcg(&g_validb[tid]);
        #pragma unroll
        for (int o = 16; o; o >>= 1) {
            lp += __shfl_down_sync(0xffffffffu, lp, o);
            c  += __shfl_down_sync(0xffffffffu, c, o);
        }
        if (tid == 0) out[0] = (c > 0) ? (lp / (float)(c > 1 ? c : 1)) : 0.0f;
    }
}

// ---------------- launch ----------------
extern "C" void kernel_launch(void* const* d_in, const int* in_sizes, int n_in,
                              void* d_out, int out_size) {
    const float* preds  = (const float*)d_in[0];
    const float* labels = (const float*)d_in[1];
    const float* images = (const float*)d_in[2];
    float* out = (float*)d_out;
    (void)in_sizes; (void)n_in; (void)out_size;

    dim3 grid(NSTR, BATCH);                    // 32 x 32 = 1024 blocks
    fusedKernel<<<grid, 256>>>(labels, images, preds, out);
}

// round 8
// speedup vs baseline: 1.1975x; 1.1975x over previous
#include <cuda_runtime.h>
#include <cuda_bf16.h>
#include <math.h>

#define BATCH 32
#define HW    512
#define NPIX  (HW*HW)            // 262144
#define WPR   16                 // 32-bit words per row
#define G4PB  (NPIX/4)           // 65536 float4 groups per batch
#define NTHR  254

#define ROWS  16                 // rows per strip
#define NSTR  (HW/ROWS)          // 32 strips
#define HALO  (ROWS+4)           // 20
#define NLW   (HALO*WPR)         // 320 halo words
#define SW    (ROWS*WPR)         // 256 strip words (== blockDim)
#define CAP   (SW*8)             // 2048 staged entries max

// ---------------- device scratch (overwrite-style; counter self-resets via wrap) ----------------
__device__ unsigned g_histp[BATCH][NSTR][256];   // otsu-hist partials
__device__ unsigned g_ccnt [BATCH][NSTR][256];   // class-bin count partials
__device__ float    g_cp   [BATCH][NSTR][256];   // class-bin sum(p)
__device__ float    g_cp2  [BATCH][NSTR][256];   // class-bin sum(p^2)
__device__ unsigned g_cntp [BATCH][NSTR];        // mask-count partials
__device__ float    g_lossper[BATCH];
__device__ int      g_validb[BATCH];
__device__ unsigned g_done;                      // wraps 0..BATCH-1

// ======== K1: pack + dilate + stage + gather + 4 histograms (no fences, no elections) ========
__global__ __launch_bounds__(256) void fusedKernel(const float* __restrict__ labels,
                                                   const float* __restrict__ images,
                                                   const float* __restrict__ preds) {
    const int b = blockIdx.y, strip = blockIdx.x;
    const int row0 = strip * ROWS;
    const int tid = threadIdx.x, lane = tid & 31, warp = tid >> 5;

    __shared__ unsigned lw[NLW];
    __shared__ unsigned hwv[NLW];
    __shared__ unsigned stage[CAP];
    __shared__ unsigned sh_hist[256];
    __shared__ unsigned cls_cnt[256];
    __shared__ float    cls_p[256];
    __shared__ float    cls_p2[256];
    __shared__ unsigned s_n;
    __shared__ unsigned wcnt[8];

    sh_hist[tid] = 0u; cls_cnt[tid] = 0u; cls_p[tid] = 0.0f; cls_p2[tid] = 0.0f;
    if (tid == 0) s_n = 0u;
    __syncthreads();

    // ---- phase A: pack label bits, one full 32-bit word per thread, 8 unrolled loads (MLP=8) ----
    const float4* lab4 = (const float4*)labels + (size_t)b * G4PB;
    for (int w = tid; w < NLW; w += 256) {
        int r = w >> 4, wc = w & 15;
        int grow = row0 - 2 + r;
        unsigned word = 0u;
        if (grow >= 0 && grow < HW) {
            const float4* p = lab4 + grow * 128 + wc * 8;
            #pragma unroll
            for (int k = 0; k < 8; k++) {
                float4 v = __ldg(p + k);
                unsigned nib = (unsigned)(v.x > 0.0f) | ((unsigned)(v.y > 0.0f) << 1)
                             | ((unsigned)(v.z > 0.0f) << 2) | ((unsigned)(v.w > 0.0f) << 3);
                word |= nib << (4 * k);
            }
        }
        lw[w] = word;
    }
    __syncthreads();

    // ---- phase B: horizontal dilation radius 2 ----
    for (int w = tid; w < NLW; w += 256) {
        int wc = w & 15;
        unsigned C = lw[w];
        unsigned L = wc ? lw[w - 1] : 0u;
        unsigned R = (wc < 15) ? lw[w + 1] : 0u;
        hwv[w] = C | (C << 1) | (C << 2) | (C >> 1) | (C >> 2)
               | (L >> 31) | (L >> 30) | (R << 31) | (R << 30);
    }
    __syncthreads();

    // ---- phase C: vertical OR + count + warp-aggregated staging (1 word/thread) ----
    {
        int w = tid;
        int r = w >> 4, wc = w & 15;
        unsigned m = hwv[w] | hwv[w + 16] | hwv[w + 32] | hwv[w + 48] | hwv[w + 64];
        unsigned cnt = __popc(m);

        unsigned nz = 0;
        #pragma unroll
        for (int k = 0; k < 8; k++) if ((m >> (k * 4)) & 0xFu) nz |= 1u << k;
        unsigned ne = __popc(nz);

        unsigned off = ne;
        #pragma unroll
        for (int o = 1; o < 32; o <<= 1) {
            unsigned v = __shfl_up_sync(0xffffffffu, off, o);
            if (lane >= o) off += v;
        }
        unsigned tot = __shfl_sync(0xffffffffu, off, 31);
        unsigned exc = off - ne;
        unsigned base = 0;
        if (lane == 31) base = atomicAdd(&s_n, tot);
        base = __shfl_sync(0xffffffffu, base, 31);

        unsigned gw8 = ((row0 + r) * WPR + wc) * 8;
        unsigned pos = base + exc;
        #pragma unroll
        for (int k = 0; k < 8; k++) if (nz & (1u << k)) {
            unsigned nib = (m >> (k * 4)) & 0xFu;
            stage[pos++] = (nib << 16) | (gw8 + k);
        }

        #pragma unroll
        for (int o = 16; o; o >>= 1) cnt += __shfl_down_sync(0xffffffffu, cnt, o);
        if (lane == 0) wcnt[warp] = cnt;
    }
    __syncthreads();

    // ---- phase D: gather img+pred at active groups, build the 4 histograms ----
    const unsigned n = s_n;
    const float4* img4 = (const float4*)images + (size_t)b * G4PB;
    const float4* prd4 = (const float4*)preds  + (size_t)b * G4PB;
    const float SCALEF = 256.0f / 255.0f;
    for (unsigned i = tid; i < n; i += 256) {
        unsigned e = stage[i];
        unsigned g = e & 0xFFFFu, nib = e >> 16;
        float4 iv = __ldg(img4 + g);
        float4 pv = __ldg(prd4 + g);
        float is[4] = {iv.x, iv.y, iv.z, iv.w};
        float ps[4] = {pv.x, pv.y, pv.z, pv.w};
        #pragma unroll
        for (int k = 0; k < 4; k++) if (nib & (1u << k)) {
            float v255 = is[k] * 255.0f;
            int idx = (int)floorf(v255 * SCALEF);          // otsu bin (== reference)
            idx = idx < 0 ? 0 : (idx > 255 ? 255 : idx);
            atomicAdd(&sh_hist[idx], 1u);
            int j = (int)floorf(v255);                     // class bin: floor(im*255)
            j = j < 0 ? 0 : (j > 255 ? 255 : j);
            float p = ps[k];
            atomicAdd(&cls_cnt[j], 1u);
            atomicAdd(&cls_p[j], p);
            atomicAdd(&cls_p2[j], p * p);
        }
    }
    __syncthreads();

    // ---- plain partial stores (no fences) ----
    g_histp[b][strip][tid] = sh_hist[tid];
    g_ccnt [b][strip][tid] = cls_cnt[tid];
    g_cp   [b][strip][tid] = cls_p[tid];
    g_cp2  [b][strip][tid] = cls_p2[tid];
    if (tid == 0) {
        unsigned t = 0;
        #pragma unroll
        for (int i = 0; i < 8; i++) t += wcnt[i];
        g_cntp[b][strip] = t;
    }
}

// ======== K2: per-batch Otsu + closed-form loss; last of 32 blocks writes scalar ========
__global__ __launch_bounds__(256) void otsuLossKernel(float* __restrict__ out) {
    const int b = blockIdx.x, tid = threadIdx.x;

    __shared__ float h[256], a[256], cmv[256];
    __shared__ float term2[NTHR];
    __shared__ unsigned char w2pos[NTHR];
    __shared__ float sbest[256];
    __shared__ int   sidx[256];
    __shared__ float red[256];
    __shared__ float s_total;
    __shared__ int   s_k1, s_k2;
    __shared__ unsigned s_rank;

    // sum per-strip partials (all 4 arrays)
    unsigned hc = 0, cc = 0;
    float cp = 0.0f, cq = 0.0f;
    #pragma unroll
    for (int s = 0; s < NSTR; s++) {
        hc += g_histp[b][s][tid];
        cc += g_ccnt [b][s][tid];
        cp += g_cp   [b][s][tid];
        cq += g_cp2  [b][s][tid];
    }
    if (tid == 0) {
        unsigned t = 0;
        #pragma unroll
        for (int s = 0; s < NSTR; s++) t += g_cntp[b][s];
        s_total = (float)t;
    }
    __syncthreads();
    h[tid] = (float)hc / s_total;
    __syncthreads();

    if (tid == 0) {                            // sequential cumsum == jnp order
        float c = 0.0f, c2 = 0.0f;
        for (int i = 0; i < 256; i++) {
            c  += h[i];              a[i]   = c;
            c2 += h[i] * (float)i;   cmv[i] = c2;
        }
    }
    __syncthreads();

    const float tm = cmv[255];
    const float s = 1e-8f;
    if (tid < NTHR) {
        float cb = a[tid], w2 = 1.0f - cb;
        float mean2 = (tm - cmv[tid]) / (w2 + s);
        float d2 = mean2 - tm;
        term2[tid] = w2 * (d2 * d2);
        w2pos[tid] = w2 > 0.0f;
    }
    __syncthreads();

    float best = -1.0f;
    int bflat = 0x7fffffff;
    if (tid < NTHR) {
        const int i = tid;
        float w0 = a[i], m0 = cmv[i];
        float mean0 = m0 / (w0 + s);
        float d0 = mean0 - tm;
        float term0 = w0 * (d0 * d0);
        bool p0 = w0 > 0.0f;
        for (int j = 0; j < NTHR; j++) {
            float w1 = a[j] - w0;
            float mean1 = (cmv[j] - m0) / (w1 + s);
            float d1 = mean1 - tm;
            float bv = term0 + w1 * (d1 * d1) + term2[j];
            bv = (p0 && w1 > 0.0f && w2pos[j]) ? bv : 0.0f;
            if (bv > best) { best = bv; bflat = i * NTHR + j; }
        }
    }
    sbest[tid] = best; sidx[tid] = bflat;
    __syncthreads();
    for (int st = 128; st; st >>= 1) {         // min-flat tie-break == jnp.argmax
        if (tid < st) {
            if (sbest[tid + st] > sbest[tid] ||
                (sbest[tid + st] == sbest[tid] && sidx[tid + st] < sidx[tid])) {
                sbest[tid] = sbest[tid + st];
                sidx[tid]  = sidx[tid + st];
            }
        }
        __syncthreads();
    }
    if (tid == 0) {
        int am = sidx[0];
        s_k1 = am / NTHR + 1;                  // im >= t1  <=>  j >= k1
        s_k2 = am % NTHR + 1;
    }
    __syncthreads();

    // closed-form loss: sum_j [ sum(p^2) + (j>=k2 ? cnt-2*sum(p) : j>=k1 ? 0.25*cnt-sum(p) : 0) ]
    float term = cq;
    if (tid >= s_k2)      term += (float)cc - 2.0f * cp;
    else if (tid >= s_k1) term += 0.25f * (float)cc - cp;
    red[tid] = term;
    __syncthreads();
    for (int st = 128; st; st >>= 1) {
        if (tid < st) red[tid] += red[tid + st];
        __syncthreads();
    }
    if (tid == 0) {
        float sm = s_total + 1e-8f;
        bool valid = sm > 1e-8f;
        g_lossper[b] = valid ? (red[0] / sm) : 0.0f;
        g_validb[b] = valid ? 1 : 0;
    }

    // ---- election among 32 blocks: last one writes the scalar ----
    __threadfence();
    __syncthreads();
    if (tid == 0) s_rank = atomicInc(&g_done, BATCH - 1);   // wraps -> replay safe
    __syncthreads();
    if (s_rank != BATCH - 1) return;
    __threadfence();

    if (tid < 32) {
        float lp = __ldcg(&g_lossper[tid]);
        int   c  = __ldcg(&g_validb[tid]);
        #pragma unroll
        for (int o = 16; o; o >>= 1) {
            lp += __shfl_down_sync(0xffffffffu, lp, o);
            c  += __shfl_down_sync(0xffffffffu, c, o);
        }
        if (tid == 0) out[0] = (c > 0) ? (lp / (float)(c > 1 ? c : 1)) : 0.0f;
    }
}

// ---------------- launch ----------------
extern "C" void kernel_launch(void* const* d_in, const int* in_sizes, int n_in,
                              void* d_out, int out_size) {
    const float* preds  = (const float*)d_in[0];
    const float* labels = (const float*)d_in[1];
    const float* images = (const float*)d_in[2];
    float* out = (float*)d_out;
    (void)in_sizes; (void)n_in; (void)out_size;

    dim3 grid(NSTR, BATCH);                    // 32 x 32 = 1024 blocks
    fusedKernel<<<grid, 256>>>(labels, images, preds);
    otsuLossKernel<<<BATCH, 256>>>(out);
}

// round 9
// speedup vs baseline: 1.8194x; 1.5194x over previous
#include <cuda_runtime.h>
#include <cuda_bf16.h>
#include <math.h>

#define BATCH 32
#define HW    512
#define NPIX  (HW*HW)            // 262144
#define WPR   16                 // 32-bit words per row
#define G4PB  (NPIX/4)           // 65536 float4 groups per batch
#define NTHR  254

#define ROWS  16                 // rows per strip
#define NSTR  (HW/ROWS)          // 32 strips
#define HALO  (ROWS+4)           // 20
#define NLW   (HALO*WPR)         // 320 halo words
#define SW    (ROWS*WPR)         // 256 strip words (== blockDim)
#define CAP   (SW*8)             // 2048 staged entries max

#define NCHUNK 8                 // otsu-search blocks per batch (32 i's each)

// ---------------- device scratch (overwrite-style; counter self-resets via wrap) ----------------
__device__ unsigned g_histp[BATCH][NSTR][256];   // otsu-hist partials
__device__ unsigned g_ccnt [BATCH][NSTR][256];   // class-bin count partials
__device__ float    g_cp   [BATCH][NSTR][256];   // class-bin sum(p)
__device__ float    g_cp2  [BATCH][NSTR][256];   // class-bin sum(p^2)
__device__ unsigned g_cntp [BATCH][NSTR];        // mask-count partials
__device__ unsigned long long g_amax[BATCH];     // packed argmax key (reset by K1)
__device__ float    g_lossper[BATCH];
__device__ int      g_validb[BATCH];
__device__ unsigned g_done;                      // wraps 0..BATCH-1

// ======== K1: pack + dilate + stage + gather + 4 histograms ========
__global__ __launch_bounds__(256) void fusedKernel(const float* __restrict__ labels,
                                                   const float* __restrict__ images,
                                                   const float* __restrict__ preds) {
    const int b = blockIdx.y, strip = blockIdx.x;
    const int row0 = strip * ROWS;
    const int tid = threadIdx.x, lane = tid & 31, warp = tid >> 5;

    __shared__ unsigned lw[NLW];
    __shared__ unsigned hwv[NLW];
    __shared__ unsigned stage[CAP];
    __shared__ unsigned sh_hist[256];
    __shared__ unsigned cls_cnt[256];
    __shared__ float    cls_p[256];
    __shared__ float    cls_p2[256];
    __shared__ unsigned s_n;
    __shared__ unsigned wcnt[8];

    sh_hist[tid] = 0u; cls_cnt[tid] = 0u; cls_p[tid] = 0.0f; cls_p2[tid] = 0.0f;
    if (tid == 0) s_n = 0u;
    if (strip == 0 && tid == 0) g_amax[b] = 0ull;      // reset before K2 (kernel boundary orders it)
    __syncthreads();

    // ---- phase A: pack label bits, one 32-bit word per thread, 8 unrolled loads (MLP=8) ----
    const float4* lab4 = (const float4*)labels + (size_t)b * G4PB;
    for (int w = tid; w < NLW; w += 256) {
        int r = w >> 4, wc = w & 15;
        int grow = row0 - 2 + r;
        unsigned word = 0u;
        if (grow >= 0 && grow < HW) {
            const float4* p = lab4 + grow * 128 + wc * 8;
            #pragma unroll
            for (int k = 0; k < 8; k++) {
                float4 v = __ldg(p + k);
                unsigned nib = (unsigned)(v.x > 0.0f) | ((unsigned)(v.y > 0.0f) << 1)
                             | ((unsigned)(v.z > 0.0f) << 2) | ((unsigned)(v.w > 0.0f) << 3);
                word |= nib << (4 * k);
            }
        }
        lw[w] = word;
    }
    __syncthreads();

    // ---- phase B: horizontal dilation radius 2 ----
    for (int w = tid; w < NLW; w += 256) {
        int wc = w & 15;
        unsigned C = lw[w];
        unsigned L = wc ? lw[w - 1] : 0u;
        unsigned R = (wc < 15) ? lw[w + 1] : 0u;
        hwv[w] = C | (C << 1) | (C << 2) | (C >> 1) | (C >> 2)
               | (L >> 31) | (L >> 30) | (R << 31) | (R << 30);
    }
    __syncthreads();

    // ---- phase C: vertical OR + count + warp-aggregated staging (1 word/thread) ----
    {
        int w = tid;
        int r = w >> 4, wc = w & 15;
        unsigned m = hwv[w] | hwv[w + 16] | hwv[w + 32] | hwv[w + 48] | hwv[w + 64];
        unsigned cnt = __popc(m);

        unsigned nz = 0;
        #pragma unroll
        for (int k = 0; k < 8; k++) if ((m >> (k * 4)) & 0xFu) nz |= 1u << k;
        unsigned ne = __popc(nz);

        unsigned off = ne;
        #pragma unroll
        for (int o = 1; o < 32; o <<= 1) {
            unsigned v = __shfl_up_sync(0xffffffffu, off, o);
            if (lane >= o) off += v;
        }
        unsigned tot = __shfl_sync(0xffffffffu, off, 31);
        unsigned exc = off - ne;
        unsigned base = 0;
        if (lane == 31) base = atomicAdd(&s_n, tot);
        base = __shfl_sync(0xffffffffu, base, 31);

        unsigned gw8 = ((row0 + r) * WPR + wc) * 8;
        unsigned pos = base + exc;
        #pragma unroll
        for (int k = 0; k < 8; k++) if (nz & (1u << k)) {
            unsigned nib = (m >> (k * 4)) & 0xFu;
            stage[pos++] = (nib << 16) | (gw8 + k);
        }

        #pragma unroll
        for (int o = 16; o; o >>= 1) cnt += __shfl_down_sync(0xffffffffu, cnt, o);
        if (lane == 0) wcnt[warp] = cnt;
    }
    __syncthreads();

    // ---- phase D: gather img+pred at active groups, build the 4 histograms ----
    const unsigned n = s_n;
    const float4* img4 = (const float4*)images + (size_t)b * G4PB;
    const float4* prd4 = (const float4*)preds  + (size_t)b * G4PB;
    const float SCALEF = 256.0f / 255.0f;
    for (unsigned i = tid; i < n; i += 256) {
        unsigned e = stage[i];
        unsigned g = e & 0xFFFFu, nib = e >> 16;
        float4 iv = __ldg(img4 + g);
        float4 pv = __ldg(prd4 + g);
        float is[4] = {iv.x, iv.y, iv.z, iv.w};
        float ps[4] = {pv.x, pv.y, pv.z, pv.w};
        #pragma unroll
        for (int k = 0; k < 4; k++) if (nib & (1u << k)) {
            float v255 = is[k] * 255.0f;
            int idx = (int)floorf(v255 * SCALEF);          // otsu bin (== reference)
            idx = idx < 0 ? 0 : (idx > 255 ? 255 : idx);
            atomicAdd(&sh_hist[idx], 1u);
            int j = (int)floorf(v255);                     // class bin: floor(im*255)
            j = j < 0 ? 0 : (j > 255 ? 255 : j);
            float p = ps[k];
            atomicAdd(&cls_cnt[j], 1u);
            atomicAdd(&cls_p[j], p);
            atomicAdd(&cls_p2[j], p * p);
        }
    }
    __syncthreads();

    g_histp[b][strip][tid] = sh_hist[tid];
    g_ccnt [b][strip][tid] = cls_cnt[tid];
    g_cp   [b][strip][tid] = cls_p[tid];
    g_cp2  [b][strip][tid] = cls_p2[tid];
    if (tid == 0) {
        unsigned t = 0;
        #pragma unroll
        for (int i = 0; i < 8; i++) t += wcnt[i];
        g_cntp[b][strip] = t;
    }
}

// ======== K2: parallel Otsu search — 8 blocks per batch, atomicMax argmax ========
__global__ __launch_bounds__(256) void otsuSearchKernel() {
    const int b = blockIdx.y, chunk = blockIdx.x, tid = threadIdx.x;
    const int lane = tid & 31, warp = tid >> 5;

    __shared__ float a[256], cmv[256];
    __shared__ float term2[256];
    __shared__ unsigned char w2pos[256];
    __shared__ float s_total;
    __shared__ unsigned long long wkey[8];

    // hist partial sum + total
    unsigned hc = 0;
    #pragma unroll
    for (int s = 0; s < NSTR; s++) hc += g_histp[b][s][tid];
    if (tid == 0) {
        unsigned t = 0;
        #pragma unroll
        for (int s = 0; s < NSTR; s++) t += g_cntp[b][s];
        s_total = (float)t;
    }
    __syncthreads();
    float hv = (float)hc / s_total;
    a[tid] = hv;
    cmv[tid] = hv * (float)tid;
    __syncthreads();

    // Kogge-Stone inclusive scan (both arrays)
    #pragma unroll
    for (int o = 1; o < 256; o <<= 1) {
        float va = 0.0f, vc = 0.0f;
        if (tid >= o) { va = a[tid - o]; vc = cmv[tid - o]; }
        __syncthreads();
        if (tid >= o) { a[tid] += va; cmv[tid] += vc; }
        __syncthreads();
    }

    const float tm = cmv[255];
    const float s = 1e-8f;
    {   // per-j precompute (j == tid)
        float cb = a[tid], w2 = 1.0f - cb;
        float mean2 = (tm - cmv[tid]) / (w2 + s);
        float d2 = mean2 - tm;
        term2[tid] = w2 * (d2 * d2);
        w2pos[tid] = w2 > 0.0f;
    }
    __syncthreads();

    // each thread: one i, 32 consecutive j's
    const int i = chunk * 32 + (tid >> 3);
    const int j0 = (tid & 7) * 32;
    unsigned long long key = 0ull;             // bv=0, worst flat
    if (i < NTHR) {
        float w0 = a[i], m0 = cmv[i];
        float mean0 = m0 / (w0 + s);
        float d0 = mean0 - tm;
        float term0 = w0 * (d0 * d0);
        bool p0 = w0 > 0.0f;
        float best = -1.0f; int bflat = 0x7fffffff;
        #pragma unroll 4
        for (int j = j0; j < j0 + 32 && j < NTHR; j++) {
            float w1 = a[j] - w0;
            float mean1 = (cmv[j] - m0) / (w1 + s);
            float d1 = mean1 - tm;
            float bv = term0 + w1 * (d1 * d1) + term2[j];
            bv = (p0 && w1 > 0.0f && w2pos[j]) ? bv : 0.0f;
            if (bv > best) { best = bv; bflat = i * NTHR + j; }   // first max (j asc)
        }
        if (best < 0.0f) best = 0.0f;
        key = ((unsigned long long)__float_as_uint(best) << 32)
            | (unsigned long long)(0x7FFFFFFFu - (unsigned)bflat);
    }
    // block reduce max-key
    #pragma unroll
    for (int o = 16; o; o >>= 1) {
        unsigned long long k2 = __shfl_down_sync(0xffffffffu, key, o);
        if (k2 > key) key = k2;
    }
    if (lane == 0) wkey[warp] = key;
    __syncthreads();
    if (tid == 0) {
        unsigned long long k = wkey[0];
        #pragma unroll
        for (int w = 1; w < 8; w++) if (wkey[w] > k) k = wkey[w];
        atomicMax(&g_amax[b], k);
    }
}

// ======== K3: closed-form loss per batch + final scalar (election among 32 blocks) ========
__global__ __launch_bounds__(256) void lossFinalKernel(float* __restrict__ out) {
    const int b = blockIdx.x, tid = threadIdx.x;
    __shared__ float red[256];
    __shared__ float s_total;
    __shared__ int s_k1, s_k2;
    __shared__ unsigned s_rank;

    if (tid == 0) {
        unsigned long long key = g_amax[b];
        int am = (int)(0x7FFFFFFFu - (unsigned)(key & 0xFFFFFFFFu));
        s_k1 = am / NTHR + 1;                  // im >= t1  <=>  j >= k1
        s_k2 = am % NTHR + 1;
        unsigned t = 0;
        #pragma unroll
        for (int s = 0; s < NSTR; s++) t += g_cntp[b][s];
        s_total = (float)t;
    }
    __syncthreads();

    unsigned cc = 0; float cp = 0.0f, cq = 0.0f;
    #pragma unroll
    for (int s = 0; s < NSTR; s++) {
        cc += g_ccnt[b][s][tid];
        cp += g_cp  [b][s][tid];
        cq += g_cp2 [b][s][tid];
    }
    float term = cq;
    if (tid >= s_k2)      term += (float)cc - 2.0f * cp;     // (1-p)^2
    else if (tid >= s_k1) term += 0.25f * (float)cc - cp;    // (0.5-p)^2
    red[tid] = term;
    __syncthreads();
    for (int st = 128; st; st >>= 1) {
        if (tid < st) red[tid] += red[tid + st];
        __syncthreads();
    }
    if (tid == 0) {
        float sm = s_total + 1e-8f;
        bool valid = sm > 1e-8f;
        g_lossper[b] = valid ? (red[0] / sm) : 0.0f;
        g_validb[b] = valid ? 1 : 0;
    }

    __threadfence();
    __syncthreads();
    if (tid == 0) s_rank = atomicInc(&g_done, BATCH - 1);    // wraps -> replay safe
    __syncthreads();
    if (s_rank != BATCH - 1) return;
    __threadfence();

    if (tid < 32) {
        float lp = __ldcg(&g_lossper[tid]);
        int   c  = __ldcg(&g_validb[tid]);
        #pragma unroll
        for (int o = 16; o; o >>= 1) {
            lp += __shfl_down_sync(0xffffffffu, lp, o);
            c  += __shfl_down_sync(0xffffffffu, c, o);
        }
        if (tid == 0) out[0] = (c > 0) ? (lp / (float)(c > 1 ? c : 1)) : 0.0f;
    }
}

// ---------------- launch ----------------
extern "C" void kernel_launch(void* const* d_in, const int* in_sizes, int n_in,
                              void* d_out, int out_size) {
    const float* preds  = (const float*)d_in[0];
    const float* labels = (const float*)d_in[1];
    const float* images = (const float*)d_in[2];
    float* out = (float*)d_out;
    (void)in_sizes; (void)n_in; (void)out_size;

    fusedKernel<<<dim3(NSTR, BATCH), 256>>>(labels, images, preds);
    otsuSearchKernel<<<dim3(NCHUNK, BATCH), 256>>>();
    lossFinalKernel<<<BATCH, 256>>>(out);
}

// round 10
// speedup vs baseline: 1.8660x; 1.0256x over previous
#include <cuda_runtime.h>
#include <cuda_bf16.h>
#include <math.h>

#define BATCH 32
#define HW    512
#define NPIX  (HW*HW)            // 262144
#define WPR   16                 // 32-bit words per row
#define G4PB  (NPIX/4)           // 65536 float4 groups per batch
#define NTHR  254

#define ROWS  16                 // rows per strip
#define NSTR  (HW/ROWS)          // 32 strips
#define HALO  (ROWS+4)           // 20
#define NLW   (HALO*WPR)         // 320 halo words
#define SW    (ROWS*WPR)         // 256 strip words (== blockDim)
#define CAP   (SW*8)             // 2048 staged entries max

#define NCHUNK 8                 // otsu-search blocks per batch (32 i's each)

// ---------------- device scratch (overwrite-style; counters self-reset via wrap) ----------------
__device__ unsigned g_histp[BATCH][NSTR][256];   // otsu-hist partials
__device__ unsigned g_ccnt [BATCH][NSTR][256];   // class-bin count partials
__device__ float    g_cp   [BATCH][NSTR][256];   // class-bin sum(p)
__device__ float    g_cp2  [BATCH][NSTR][256];   // class-bin sum(p^2)
__device__ unsigned g_cntp [BATCH][NSTR];        // mask-count partials
__device__ unsigned long long g_amax[BATCH];     // packed argmax key (reset by K1)
__device__ float    g_lossper[BATCH];
__device__ int      g_validb[BATCH];
__device__ unsigned g_done1[BATCH];              // wraps 0..NCHUNK-1
__device__ unsigned g_done2;                     // wraps 0..BATCH-1

// ======== K1: pack + dilate + stage + gather + 4 histograms ========
__global__ __launch_bounds__(256) void fusedKernel(const float* __restrict__ labels,
                                                   const float* __restrict__ images,
                                                   const float* __restrict__ preds) {
    const int b = blockIdx.y, strip = blockIdx.x;
    const int row0 = strip * ROWS;
    const int tid = threadIdx.x, lane = tid & 31, warp = tid >> 5;

    __shared__ unsigned lw[NLW];
    __shared__ unsigned hwv[NLW];
    __shared__ unsigned stage[CAP];
    __shared__ unsigned sh_hist[256];
    __shared__ unsigned cls_cnt[256];
    __shared__ float    cls_p[256];
    __shared__ float    cls_p2[256];
    __shared__ unsigned s_n;
    __shared__ unsigned wcnt[8];

    sh_hist[tid] = 0u; cls_cnt[tid] = 0u; cls_p[tid] = 0.0f; cls_p2[tid] = 0.0f;
    if (tid == 0) s_n = 0u;
    if (strip == 0 && tid == 0) g_amax[b] = 0ull;      // reset before K2 (kernel boundary orders it)
    __syncthreads();

    // ---- phase A: pack label bits, one 32-bit word per thread, 8 unrolled loads (MLP=8) ----
    const float4* lab4 = (const float4*)labels + (size_t)b * G4PB;
    for (int w = tid; w < NLW; w += 256) {
        int r = w >> 4, wc = w & 15;
        int grow = row0 - 2 + r;
        unsigned word = 0u;
        if (grow >= 0 && grow < HW) {
            const float4* p = lab4 + grow * 128 + wc * 8;
            #pragma unroll
            for (int k = 0; k < 8; k++) {
                float4 v = __ldg(p + k);
                unsigned nib = (unsigned)(v.x > 0.0f) | ((unsigned)(v.y > 0.0f) << 1)
                             | ((unsigned)(v.z > 0.0f) << 2) | ((unsigned)(v.w > 0.0f) << 3);
                word |= nib << (4 * k);
            }
        }
        lw[w] = word;
    }
    __syncthreads();

    // ---- phase B: horizontal dilation radius 2 ----
    for (int w = tid; w < NLW; w += 256) {
        int wc = w & 15;
        unsigned C = lw[w];
        unsigned L = wc ? lw[w - 1] : 0u;
        unsigned R = (wc < 15) ? lw[w + 1] : 0u;
        hwv[w] = C | (C << 1) | (C << 2) | (C >> 1) | (C >> 2)
               | (L >> 31) | (L >> 30) | (R << 31) | (R << 30);
    }
    __syncthreads();

    // ---- phase C: vertical OR + count + warp-aggregated staging (1 word/thread) ----
    {
        int w = tid;
        int r = w >> 4, wc = w & 15;
        unsigned m = hwv[w] | hwv[w + 16] | hwv[w + 32] | hwv[w + 48] | hwv[w + 64];
        unsigned cnt = __popc(m);

        unsigned nz = 0;
        #pragma unroll
        for (int k = 0; k < 8; k++) if ((m >> (k * 4)) & 0xFu) nz |= 1u << k;
        unsigned ne = __popc(nz);

        unsigned off = ne;
        #pragma unroll
        for (int o = 1; o < 32; o <<= 1) {
            unsigned v = __shfl_up_sync(0xffffffffu, off, o);
            if (lane >= o) off += v;
        }
        unsigned tot = __shfl_sync(0xffffffffu, off, 31);
        unsigned exc = off - ne;
        unsigned base = 0;
        if (lane == 31) base = atomicAdd(&s_n, tot);
        base = __shfl_sync(0xffffffffu, base, 31);

        unsigned gw8 = ((row0 + r) * WPR + wc) * 8;
        unsigned pos = base + exc;
        #pragma unroll
        for (int k = 0; k < 8; k++) if (nz & (1u << k)) {
            unsigned nib = (m >> (k * 4)) & 0xFu;
            stage[pos++] = (nib << 16) | (gw8 + k);
        }

        #pragma unroll
        for (int o = 16; o; o >>= 1) cnt += __shfl_down_sync(0xffffffffu, cnt, o);
        if (lane == 0) wcnt[warp] = cnt;
    }
    __syncthreads();

    // ---- phase D: gather img+pred at active groups, build the 4 histograms ----
    const unsigned n = s_n;
    const float4* img4 = (const float4*)images + (size_t)b * G4PB;
    const float4* prd4 = (const float4*)preds  + (size_t)b * G4PB;
    const float SCALEF = 256.0f / 255.0f;
    for (unsigned i = tid; i < n; i += 256) {
        unsigned e = stage[i];
        unsigned g = e & 0xFFFFu, nib = e >> 16;
        float4 iv = __ldg(img4 + g);
        float4 pv = __ldg(prd4 + g);
        float is[4] = {iv.x, iv.y, iv.z, iv.w};
        float ps[4] = {pv.x, pv.y, pv.z, pv.w};
        #pragma unroll
        for (int k = 0; k < 4; k++) if (nib & (1u << k)) {
            float v255 = is[k] * 255.0f;
            int idx = (int)floorf(v255 * SCALEF);          // otsu bin (== reference)
            idx = idx < 0 ? 0 : (idx > 255 ? 255 : idx);
            atomicAdd(&sh_hist[idx], 1u);
            int j = (int)floorf(v255);                     // class bin: floor(im*255)
            j = j < 0 ? 0 : (j > 255 ? 255 : j);
            float p = ps[k];
            atomicAdd(&cls_cnt[j], 1u);
            atomicAdd(&cls_p[j], p);
            atomicAdd(&cls_p2[j], p * p);
        }
    }
    __syncthreads();

    g_histp[b][strip][tid] = sh_hist[tid];
    g_ccnt [b][strip][tid] = cls_cnt[tid];
    g_cp   [b][strip][tid] = cls_p[tid];
    g_cp2  [b][strip][tid] = cls_p2[tid];
    if (tid == 0) {
        unsigned t = 0;
        #pragma unroll
        for (int i = 0; i < 8; i++) t += wcnt[i];
        g_cntp[b][strip] = t;
    }
}

// ======== K2: parallel Otsu search + (batch-last) closed-form loss + (global-last) scalar ========
__global__ __launch_bounds__(256) void otsuLossKernel(float* __restrict__ out) {
    const int b = blockIdx.y, chunk = blockIdx.x, tid = threadIdx.x;
    const int lane = tid & 31, warp = tid >> 5;

    __shared__ float a[256], cmv[256];
    __shared__ float term2[256];
    __shared__ unsigned char w2pos[256];
    __shared__ float s_total;
    __shared__ unsigned long long wkey[8];
    __shared__ unsigned s_rank, s_rank2;

    // hist partial sum + total
    unsigned hc = 0;
    #pragma unroll
    for (int s = 0; s < NSTR; s++) hc += g_histp[b][s][tid];
    if (tid == 0) {
        unsigned t = 0;
        #pragma unroll
        for (int s = 0; s < NSTR; s++) t += g_cntp[b][s];
        s_total = (float)t;
    }
    __syncthreads();
    float hv = (float)hc / s_total;
    a[tid] = hv;
    cmv[tid] = hv * (float)tid;
    __syncthreads();

    // Kogge-Stone inclusive scan (both arrays)
    #pragma unroll
    for (int o = 1; o < 256; o <<= 1) {
        float va = 0.0f, vc = 0.0f;
        if (tid >= o) { va = a[tid - o]; vc = cmv[tid - o]; }
        __syncthreads();
        if (tid >= o) { a[tid] += va; cmv[tid] += vc; }
        __syncthreads();
    }

    const float tm = cmv[255];
    const float s = 1e-8f;
    {   // per-j precompute (j == tid)
        float cb = a[tid], w2 = 1.0f - cb;
        float mean2 = (tm - cmv[tid]) / (w2 + s);
        float d2 = mean2 - tm;
        term2[tid] = w2 * (d2 * d2);
        w2pos[tid] = w2 > 0.0f;
    }
    __syncthreads();

    // each thread: one i, 32 consecutive j's
    const int i = chunk * 32 + (tid >> 3);
    const int j0 = (tid & 7) * 32;
    unsigned long long key = 0ull;
    if (i < NTHR) {
        float w0 = a[i], m0 = cmv[i];
        float mean0 = m0 / (w0 + s);
        float d0 = mean0 - tm;
        float term0 = w0 * (d0 * d0);
        bool p0 = w0 > 0.0f;
        float best = -1.0f; int bflat = 0x7fffffff;
        #pragma unroll 4
        for (int j = j0; j < j0 + 32 && j < NTHR; j++) {
            float w1 = a[j] - w0;
            float mean1 = (cmv[j] - m0) / (w1 + s);
            float d1 = mean1 - tm;
            float bv = term0 + w1 * (d1 * d1) + term2[j];
            bv = (p0 && w1 > 0.0f && w2pos[j]) ? bv : 0.0f;
            if (bv > best) { best = bv; bflat = i * NTHR + j; }   // first max (j asc)
        }
        if (best < 0.0f) best = 0.0f;
        key = ((unsigned long long)__float_as_uint(best) << 32)
            | (unsigned long long)(0x7FFFFFFFu - (unsigned)bflat);
    }
    #pragma unroll
    for (int o = 16; o; o >>= 1) {
        unsigned long long k2 = __shfl_down_sync(0xffffffffu, key, o);
        if (k2 > key) key = k2;
    }
    if (lane == 0) wkey[warp] = key;
    __syncthreads();

    // ---- election 1: among NCHUNK blocks of this batch (fences on tid 0 only) ----
    if (tid == 0) {
        unsigned long long k = wkey[0];
        #pragma unroll
        for (int w = 1; w < 8; w++) if (wkey[w] > k) k = wkey[w];
        atomicMax(&g_amax[b], k);
        __threadfence();
        s_rank = atomicInc(&g_done1[b], NCHUNK - 1);       // wraps -> replay safe
    }
    __syncthreads();
    if (s_rank != NCHUNK - 1) return;

    // ---- batch-last block: closed-form loss for batch b ----
    __shared__ int s_k1, s_k2;
    if (tid == 0) {
        __threadfence();                                   // acquire g_amax
        unsigned long long kk = g_amax[b];
        int am = (int)(0x7FFFFFFFu - (unsigned)(kk & 0xFFFFFFFFu));
        s_k1 = am / NTHR + 1;                              // im >= t1 <=> j >= k1
        s_k2 = am % NTHR + 1;
    }
    __syncthreads();

    unsigned cc = 0; float cp = 0.0f, cq = 0.0f;
    #pragma unroll
    for (int s2 = 0; s2 < NSTR; s2++) {
        cc += g_ccnt[b][s2][tid];
        cp += g_cp  [b][s2][tid];
        cq += g_cp2 [b][s2][tid];
    }
    float term = cq;
    if (tid >= s_k2)      term += (float)cc - 2.0f * cp;     // (1-p)^2
    else if (tid >= s_k1) term += 0.25f * (float)cc - cp;    // (0.5-p)^2
    float* red = a;                                          // alias scan array
    red[tid] = term;
    __syncthreads();
    for (int st = 128; st; st >>= 1) {
        if (tid < st) red[tid] += red[tid + st];
        __syncthreads();
    }

    // ---- election 2: among 32 batch-last blocks ----
    if (tid == 0) {
        float sm = s_total + 1e-8f;
        bool valid = sm > 1e-8f;
        g_lossper[b] = valid ? (red[0] / sm) : 0.0f;
        g_validb[b] = valid ? 1 : 0;
        __threadfence();
        s_rank2 = atomicInc(&g_done2, BATCH - 1);          // wraps -> replay safe
    }
    __syncthreads();
    if (s_rank2 != BATCH - 1) return;

    if (tid < 32) {
        float lp = __ldcg(&g_lossper[tid]);
        int   c  = __ldcg(&g_validb[tid]);
        #pragma unroll
        for (int o = 16; o; o >>= 1) {
            lp += __shfl_down_sync(0xffffffffu, lp, o);
            c  += __shfl_down_sync(0xffffffffu, c, o);
        }
        if (tid == 0) out[0] = (c > 0) ? (lp / (float)(c > 1 ? c : 1)) : 0.0f;
    }
}

// ---------------- launch ----------------
extern "C" void kernel_launch(void* const* d_in, const int* in_sizes, int n_in,
                              void* d_out, int out_size) {
    const float* preds  = (const float*)d_in[0];
    const float* labels = (const float*)d_in[1];
    const float* images = (const float*)d_in[2];
    float* out = (float*)d_out;
    (void)in_sizes; (void)n_in; (void)out_size;

    fusedKernel<<<dim3(NSTR, BATCH), 256>>>(labels, images, preds);
    otsuLossKernel<<<dim3(NCHUNK, BATCH), 256>>>(out);
}